// round 1
// baseline (speedup 1.0000x reference)
#include <cuda_runtime.h>
#include <cuda_bf16.h>
#include <math.h>

// Problem constants: B=4, S=2048, D=1024, H=16, hs=64
#define BATCH 4
#define SEQ   2048
#define DIM   1024
#define HEADS 16
#define HS    64
#define W3    3072   // 3*DIM

// Scratch (device globals; allocation at module load, not runtime)
__device__ float g_qkv[(size_t)BATCH * SEQ * W3];   // [B,S,3D]
__device__ float g_ctx[(size_t)BATCH * SEQ * DIM];  // [B,S,D]

// ---------------------------------------------------------------------------
// SGEMM: C[M,N] = A[M,K] @ B[K,N] + bias[N]   (all row-major, dims % 128 == 0,
// K % 16 == 0). 128x128 tile, BK=16, 256 threads, 8x8 per-thread microtile.
// ---------------------------------------------------------------------------
__global__ void __launch_bounds__(256) sgemm_bias_kernel(
    const float* __restrict__ A, const float* __restrict__ B,
    const float* __restrict__ bias, float* __restrict__ C,
    int M, int N, int K)
{
    __shared__ float As[16][132];  // transposed: As[k][m]
    __shared__ float Bs[16][128];  // natural:    Bs[k][n]

    const int tid = threadIdx.x;
    const int tx = tid & 15;       // 0..15 -> N direction
    const int ty = tid >> 4;       // 0..15 -> M direction
    const int bm = blockIdx.y * 128;
    const int bn = blockIdx.x * 128;

    float acc[8][8];
#pragma unroll
    for (int i = 0; i < 8; i++)
#pragma unroll
        for (int j = 0; j < 8; j++) acc[i][j] = 0.0f;

    for (int k0 = 0; k0 < K; k0 += 16) {
#pragma unroll
        for (int t = 0; t < 2; t++) {
            int i = tid + t * 256;           // 0..511
            // A tile: 128 rows x 4 float4
            int r  = i >> 2;
            int c4 = i & 3;
            float4 a = *(const float4*)(A + (size_t)(bm + r) * K + k0 + c4 * 4);
            As[c4 * 4 + 0][r] = a.x;
            As[c4 * 4 + 1][r] = a.y;
            As[c4 * 4 + 2][r] = a.z;
            As[c4 * 4 + 3][r] = a.w;
            // B tile: 16 rows x 32 float4
            int rb  = i >> 5;
            int cb4 = i & 31;
            *(float4*)&Bs[rb][cb4 * 4] =
                *(const float4*)(B + (size_t)(k0 + rb) * N + bn + cb4 * 4);
        }
        __syncthreads();

#pragma unroll
        for (int k = 0; k < 16; k++) {
            float ar[8], br[8];
            *(float4*)(ar)     = *(float4*)&As[k][ty * 8];
            *(float4*)(ar + 4) = *(float4*)&As[k][ty * 8 + 4];
            *(float4*)(br)     = *(float4*)&Bs[k][tx * 8];
            *(float4*)(br + 4) = *(float4*)&Bs[k][tx * 8 + 4];
#pragma unroll
            for (int i = 0; i < 8; i++)
#pragma unroll
                for (int j = 0; j < 8; j++)
                    acc[i][j] = fmaf(ar[i], br[j], acc[i][j]);
        }
        __syncthreads();
    }

    // epilogue: add bias, store
#pragma unroll
    for (int i = 0; i < 8; i++) {
        int row = bm + ty * 8 + i;
#pragma unroll
        for (int j4 = 0; j4 < 2; j4++) {
            int col = bn + tx * 8 + j4 * 4;
            float4 o;
            o.x = acc[i][j4 * 4 + 0] + bias[col + 0];
            o.y = acc[i][j4 * 4 + 1] + bias[col + 1];
            o.z = acc[i][j4 * 4 + 2] + bias[col + 2];
            o.w = acc[i][j4 * 4 + 3] + bias[col + 3];
            *(float4*)(C + (size_t)row * N + col) = o;
        }
    }
}

// ---------------------------------------------------------------------------
// Flash attention (fp32, causal). One block = (b,h, 64-query tile).
// Reads q/k/v straight out of the fused qkv buffer [B,S,3D].
// 256 threads: tx (0..15) -> 4 key cols, ty (0..15) -> 4 query rows.
// smem: Qt/Kt stored [c][row] so both QK fragments are LDS.128; Vs natural.
// ---------------------------------------------------------------------------
__global__ void __launch_bounds__(256) attn_kernel(
    const float* __restrict__ qkv, float* __restrict__ ctx)
{
    extern __shared__ float sm[];
    float (*Qt)[68] = (float(*)[68])(sm);                 // [c][qrow]
    float (*Kt)[68] = (float(*)[68])(sm + 64 * 68);       // [c][krow]
    float (*Vs)[68] = (float(*)[68])(sm + 2 * 64 * 68);   // [krow][c]
    float (*Ps)[68] = (float(*)[68])(sm + 3 * 64 * 68);   // [qrow][krow]

    const int qt = blockIdx.x;          // 0..31
    const int bh = blockIdx.y;          // 0..63
    const int b = bh >> 4;
    const int h = bh & 15;

    const float* base = qkv + (size_t)b * SEQ * W3;
    const int qoff = h * HS;
    const int koff = DIM + h * HS;
    const int voff = 2 * DIM + h * HS;

    const int tid = threadIdx.x;
    const int tx = tid & 15;
    const int ty = tid >> 4;
    const int lr = tid >> 2;     // 0..63 (row for cooperative loads)
    const int lc = tid & 3;      // 0..3  (float4-column for loads)

    // ---- load Q tile transposed: Qt[c][qrow] ----
#pragma unroll
    for (int it = 0; it < 4; it++) {
        int c4 = lc + it * 4;
        float4 v = *(const float4*)(base + (size_t)(qt * 64 + lr) * W3 + qoff + c4 * 4);
        Qt[c4 * 4 + 0][lr] = v.x;
        Qt[c4 * 4 + 1][lr] = v.y;
        Qt[c4 * 4 + 2][lr] = v.z;
        Qt[c4 * 4 + 3][lr] = v.w;
    }

    float m[4], l[4], O[4][4];
#pragma unroll
    for (int i = 0; i < 4; i++) {
        m[i] = -1e30f;
        l[i] = 0.0f;
#pragma unroll
        for (int j = 0; j < 4; j++) O[i][j] = 0.0f;
    }

    for (int kt = 0; kt <= qt; kt++) {
        // ---- load K tile transposed + V tile natural ----
#pragma unroll
        for (int it = 0; it < 4; it++) {
            int c4 = lc + it * 4;
            const float* krow = base + (size_t)(kt * 64 + lr) * W3;
            float4 kv = *(const float4*)(krow + koff + c4 * 4);
            Kt[c4 * 4 + 0][lr] = kv.x;
            Kt[c4 * 4 + 1][lr] = kv.y;
            Kt[c4 * 4 + 2][lr] = kv.z;
            Kt[c4 * 4 + 3][lr] = kv.w;
            float4 vv = *(const float4*)(krow + voff + c4 * 4);
            *(float4*)&Vs[lr][c4 * 4] = vv;
        }
        __syncthreads();

        // ---- S = Q K^T (4x4 per thread) ----
        float s[4][4];
#pragma unroll
        for (int i = 0; i < 4; i++)
#pragma unroll
            for (int j = 0; j < 4; j++) s[i][j] = 0.0f;

#pragma unroll
        for (int c = 0; c < 64; c++) {
            float4 qv = *(float4*)&Qt[c][ty * 4];
            float4 kv = *(float4*)&Kt[c][tx * 4];
            float qa[4] = {qv.x, qv.y, qv.z, qv.w};
            float ka[4] = {kv.x, kv.y, kv.z, kv.w};
#pragma unroll
            for (int i = 0; i < 4; i++)
#pragma unroll
                for (int j = 0; j < 4; j++)
                    s[i][j] = fmaf(qa[i], ka[j], s[i][j]);
        }

        const bool diag = (kt == qt);
#pragma unroll
        for (int i = 0; i < 4; i++) {
#pragma unroll
            for (int j = 0; j < 4; j++) {
                s[i][j] *= 0.125f;   // 1/sqrt(64)
                if (diag && (ty * 4 + i) < (tx * 4 + j)) s[i][j] = -1e30f;
            }
        }

        // ---- online softmax ----
#pragma unroll
        for (int i = 0; i < 4; i++) {
            float rm = fmaxf(fmaxf(s[i][0], s[i][1]), fmaxf(s[i][2], s[i][3]));
#pragma unroll
            for (int off = 1; off < 16; off <<= 1)
                rm = fmaxf(rm, __shfl_xor_sync(0xffffffffu, rm, off));
            float mn = fmaxf(m[i], rm);
            float al = __expf(m[i] - mn);
            float rs = 0.0f;
#pragma unroll
            for (int j = 0; j < 4; j++) {
                s[i][j] = __expf(s[i][j] - mn);
                rs += s[i][j];
            }
#pragma unroll
            for (int off = 1; off < 16; off <<= 1)
                rs += __shfl_xor_sync(0xffffffffu, rs, off);
            l[i] = l[i] * al + rs;
            m[i] = mn;
#pragma unroll
            for (int j = 0; j < 4; j++) O[i][j] *= al;
            float4 p = make_float4(s[i][0], s[i][1], s[i][2], s[i][3]);
            *(float4*)&Ps[ty * 4 + i][tx * 4] = p;
        }
        __syncthreads();

        // ---- O += P @ V ----
#pragma unroll
        for (int f = 0; f < 64; f++) {
            float4 vv = *(float4*)&Vs[f][tx * 4];
            float va[4] = {vv.x, vv.y, vv.z, vv.w};
            float p0 = Ps[ty * 4 + 0][f];
            float p1 = Ps[ty * 4 + 1][f];
            float p2 = Ps[ty * 4 + 2][f];
            float p3 = Ps[ty * 4 + 3][f];
#pragma unroll
            for (int j = 0; j < 4; j++) {
                O[0][j] = fmaf(p0, va[j], O[0][j]);
                O[1][j] = fmaf(p1, va[j], O[1][j]);
                O[2][j] = fmaf(p2, va[j], O[2][j]);
                O[3][j] = fmaf(p3, va[j], O[3][j]);
            }
        }
        __syncthreads();
    }

    // ---- epilogue: O / l  -> ctx[b, t, h*64 + d] ----
#pragma unroll
    for (int i = 0; i < 4; i++) {
        float inv = 1.0f / l[i];
        int row = qt * 64 + ty * 4 + i;
        float4 o = make_float4(O[i][0] * inv, O[i][1] * inv,
                               O[i][2] * inv, O[i][3] * inv);
        *(float4*)(ctx + ((size_t)b * SEQ + row) * DIM + h * HS + tx * 4) = o;
    }
}

// ---------------------------------------------------------------------------
extern "C" void kernel_launch(void* const* d_in, const int* in_sizes, int n_in,
                              void* d_out, int out_size)
{
    const float* enc    = (const float*)d_in[0];
    const float* w_attn = (const float*)d_in[1];
    const float* b_attn = (const float*)d_in[2];
    const float* w_proj = (const float*)d_in[3];
    const float* b_proj = (const float*)d_in[4];
    float* out = (float*)d_out;

    float* qkv = nullptr;
    float* ctx = nullptr;
    cudaGetSymbolAddress((void**)&qkv, g_qkv);
    cudaGetSymbolAddress((void**)&ctx, g_ctx);

    const int M = BATCH * SEQ;   // 8192

    // QKV GEMM: [8192,1024] @ [1024,3072] + bias
    {
        dim3 grid(W3 / 128, M / 128);
        sgemm_bias_kernel<<<grid, 256>>>(enc, w_attn, b_attn, qkv, M, W3, DIM);
    }

    // Attention
    {
        static const size_t smem = 4 * 64 * 68 * sizeof(float);  // 69632 B
        cudaFuncSetAttribute(attn_kernel,
                             cudaFuncAttributeMaxDynamicSharedMemorySize,
                             (int)smem);
        dim3 grid(SEQ / 64, BATCH * HEADS);
        attn_kernel<<<grid, 256, smem>>>(qkv, ctx);
    }

    // Output projection: [8192,1024] @ [1024,1024] + bias
    {
        dim3 grid(DIM / 128, M / 128);
        sgemm_bias_kernel<<<grid, 256>>>(ctx, w_proj, b_proj, out, M, DIM, DIM);
    }
}